// round 16
// baseline (speedup 1.0000x reference)
#include <cuda_runtime.h>

// Involution2d: B=8, C=256, G=4, Cpg=64, K=7, H=W=64, pad=3
// out[b,c,ho,wo] = sum_{kh,kw} in[b,c,ho+kh-3,wo+kw-3] * w[b,g,kh,kw,ho,wo] + bias[c]
//
// R15 = R11 (35.3us best) with WARP-PRIVATE smem pipeline, zero __syncthreads:
//  - each warp owns private NBUF x STAGE_CH x 10-row buffers (loads only its rows;
//    rows 4-9 duplicated between warps -> +43% L2 traffic, absorbed at 24% L2)
//  - per-warp cp.async groups + __syncwarp only -> warps fully decoupled,
//    ptxas can schedule across stage boundaries
//  - compute body, weights (196 regs), TH=4, geometry: exactly R11

#define TILE_W 32
#define TILE_H 8
#define TH 4
#define SWP 40                   // smem row stride (floats) = loaded window width
#define ROWS_W 10                // input rows per warp (TH + 6)
#define PLW (ROWS_W*SWP)         // 400 floats per channel plane (per warp)
#define WCHUNK 10                // 16B chunks per row
#define WSLOTS (ROWS_W*WCHUNK)   // 100 chunk slots per plane per warp
#define STAGE_CH 2
#define CH_PER_CTA 32
#define NSTAGES (CH_PER_CTA/STAGE_CH)   // 16
#define NBUF 4
#define CHW_B (PLW*4)            // 1600 B per channel plane (warp)
#define BUFW_B (STAGE_CH*CHW_B)  // 3200 B per buffer (warp)
#define WARP_B (NBUF*BUFW_B)     // 12800 B per warp region
#define NTHR 64
#define NSLOT 4                  // ceil(100/32)

__device__ __forceinline__ void cpa16(unsigned dst, const float* src) {
    asm volatile("cp.async.cg.shared.global [%0], [%1], 16;\n" :: "r"(dst), "l"(src));
}
__device__ __forceinline__ void cpa_commit() {
    asm volatile("cp.async.commit_group;\n" ::: "memory");
}
__device__ __forceinline__ void cpa_wait2() {
    asm volatile("cp.async.wait_group 2;\n" ::: "memory");
}
__device__ __forceinline__ unsigned long long pack2(float a, float b) {
    unsigned long long r;
    asm("mov.b64 %0, {%1, %2};" : "=l"(r) : "f"(a), "f"(b));
    return r;
}
__device__ __forceinline__ void fma2(unsigned long long& d,
                                     unsigned long long a, unsigned long long b) {
    asm("fma.rn.f32x2 %0, %1, %2, %0;" : "+l"(d) : "l"(a), "l"(b));
}
__device__ __forceinline__ float hadd2(unsigned long long v) {
    float lo, hi;
    asm("mov.b64 {%0, %1}, %2;" : "=f"(lo), "=f"(hi) : "l"(v));
    return lo + hi;
}

__global__ __launch_bounds__(NTHR, 4)
void involution2d_kernel(const float* __restrict__ input,
                         const float* __restrict__ weight,
                         const float* __restrict__ bias,
                         float* __restrict__ out)
{
    // [2 warps][NBUF][STAGE_CH][PLW] floats = 25.6 KB
    __shared__ __align__(16) float tile[2 * NBUF * STAGE_CH * PLW];

    const int tx  = threadIdx.x;            // 0..31 (lane)
    const int ty  = threadIdx.y;            // 0..1  (warp)

    int bid = blockIdx.x;
    const int half = bid & 1; bid >>= 1;    // channel half
    const int wt = bid & 1;  bid >>= 1;     // 2 tiles across W
    const int ht = bid & 7;  bid >>= 3;     // 8 tiles across H
    const int g  = bid & 3;  bid >>= 2;     // 4 groups
    const int b  = bid;                     // 8 batches

    const int ch0 = half * CH_PER_CTA;
    const int w0g = wt * TILE_W;
    const int h0g = ht * TILE_H;
    const int oy0 = ty * TH;                // 0 or 4
    const int ho0 = h0g + oy0;
    const int wo  = w0g + tx;

    // ---- compute-side window offsets (window base = w0g-4; tap j -> idx tx+1+j) ----
    const int base  = tx + 1;
    const int p     = base & 1;
    const int jp0   = p;                     // first paired tap
    const int jscal = p ? 0 : 6;             // scalar tap
    const int pairIdx = base + p;            // even -> 8B aligned
    const int scalIdx = base + jscal;

    // ---- weights: 4 rows x 49 = 196 regs/thread, parity pairing, read once ----
    unsigned long long wp[TH][7][3];
    float ws[TH][7];
    {
        const float* wb = weight + ((size_t)(b * 4 + g) * 49) * 4096 + ho0 * 64 + wo;
        #pragma unroll
        for (int t = 0; t < TH; ++t) {
            const float* wt_ = wb + t * 64;
            #pragma unroll
            for (int r = 0; r < 7; ++r) {
                #pragma unroll
                for (int m = 0; m < 3; ++m) {
                    int k = r * 7 + jp0 + 2 * m;
                    wp[t][r][m] = pack2(wt_[k * 4096], wt_[(k + 1) * 4096]);
                }
                ws[t][r] = wt_[(r * 7 + jscal) * 4096];
            }
        }
    }

    const float* inb  = input + (b * 256 + g * 64 + ch0) * 4096;
    float*       outb = out   + (b * 256 + g * 64 + ch0) * 4096;
    const float* biasb = bias + g * 64 + ch0;

    // this warp's private smem region
    const unsigned wbase =
        (unsigned)__cvta_generic_to_shared(&tile[0]) + (unsigned)ty * WARP_B;
    float* wtile = &tile[ty * (NBUF * STAGE_CH * PLW)];

    // ---- loader slots (warp-private rows): slot = row*10 + chunk ----
    // cached per-thread offsets (R11 style; recompute was slower in R14)
    int      goff[NSLOT];
    unsigned soff[NSLOT];
    bool     okm [NSLOT];
    #pragma unroll
    for (int q = 0; q < NSLOT; ++q) {
        int slot = tx + q * 32;
        okm[q] = false; goff[q] = 0; soff[q] = 0;
        if (slot < WSLOTS) {
            int row = slot / WCHUNK;
            int ck  = slot - row * WCHUNK;
            int gh  = h0g + oy0 - 3 + row;       // this warp's input row
            int gw  = w0g - 4 + 4 * ck;          // chunk fully in or fully out
            bool ok = ((unsigned)gh < 64u) && ((unsigned)gw < 64u);
            okm [q] = ok;
            goff[q] = gh * 64 + gw;
            soff[q] = (unsigned)(row * SWP + 4 * ck) * 4u;
            if (!ok) {   // halo constant zero across channels: fill all my planes once
                float* z = wtile + (row * SWP + 4 * ck);
                #pragma unroll
                for (int pl = 0; pl < NBUF * STAGE_CH; ++pl) {
                    float4* z4 = (float4*)(z + pl * PLW);
                    *z4 = make_float4(0.f, 0.f, 0.f, 0.f);
                }
            }
        }
    }
    __syncwarp();   // zero-fill visible within warp

    auto issue = [&](int stage, int bi) {
        const float* gsrc = inb + (size_t)stage * (STAGE_CH * 4096);
        const unsigned bA = wbase + (unsigned)bi * BUFW_B;
        #pragma unroll
        for (int c = 0; c < STAGE_CH; ++c) {
            const float* gc = gsrc + c * 4096;
            const unsigned pb = bA + (unsigned)c * CHW_B;
            #pragma unroll
            for (int q = 0; q < NSLOT; ++q)
                if (okm[q]) cpa16(pb + soff[q], gc + goff[q]);
        }
    };

    // ---- prologue: stages 0..2 into buffers 0..2 (per-warp groups) ----
    issue(0, 0); cpa_commit();
    issue(1, 1); cpa_commit();
    issue(2, 2); cpa_commit();

    int cb = 0;            // buffer holding stage s
    int ib = 3;            // buffer for stage s+3
    for (int s = 0; s < NSTAGES; ++s) {
        cpa_wait2();                 // my stage s landed (<=2 groups pending)
        __syncwarp();                // lanes' data visible warp-wide; prior reads done

        if (s + 3 < NSTAGES) issue(s + 3, ib);
        cpa_commit();                // empty tail groups harmless

        // ---- compute the 2 channels of stage s, 4 output rows each ----
        const float* bufp = wtile + cb * (STAGE_CH * PLW);
        #pragma unroll
        for (int c = 0; c < STAGE_CH; ++c) {
            const float* plane = bufp + c * PLW;
            const float bv = __ldg(biasb + s * STAGE_CH + c);
            unsigned long long acc[TH];
            float accs[TH];
            #pragma unroll
            for (int t = 0; t < TH; ++t) { acc[t] = 0ull; accs[t] = bv; }

            #pragma unroll
            for (int r = 0; r < ROWS_W; ++r) {       // 10 input rows (warp-private)
                const float* rowf = plane + r * SWP;
                const unsigned long long* rp =
                    (const unsigned long long*)(rowf + pairIdx);
                unsigned long long p0 = rp[0], p1 = rp[1], p2 = rp[2];
                float xs = rowf[scalIdx];
                #pragma unroll
                for (int t = 0; t < TH; ++t) {
                    if (r >= t && r <= t + 6) {      // compile-time per (r,t)
                        const int kr = r - t;
                        fma2(acc[t], p0, wp[t][kr][0]);
                        fma2(acc[t], p1, wp[t][kr][1]);
                        fma2(acc[t], p2, wp[t][kr][2]);
                        accs[t] = fmaf(xs, ws[t][kr], accs[t]);
                    }
                }
            }
            const int ch = s * STAGE_CH + c;
            float* op = outb + ch * 4096 + ho0 * 64 + wo;
            #pragma unroll
            for (int t = 0; t < TH; ++t)
                op[t * 64] = hadd2(acc[t]) + accs[t];
        }

        cb = (cb == NBUF - 1) ? 0 : cb + 1;
        ib = (ib == NBUF - 1) ? 0 : ib + 1;
    }
}

extern "C" void kernel_launch(void* const* d_in, const int* in_sizes, int n_in,
                              void* d_out, int out_size)
{
    const float* input  = (const float*)d_in[0];
    const float* weight = (const float*)d_in[1];
    const float* bias   = (const float*)d_in[2];
    float*       out    = (float*)d_out;

    dim3 block(TILE_W, 2, 1);                 // 64 threads = 2 warps
    dim3 grid(8 * 4 * 8 * 2 * 2, 1, 1);       // B*G*Ht*Wt*chhalves = 1024
    involution2d_kernel<<<grid, block>>>(input, weight, bias, out);
}